// round 4
// baseline (speedup 1.0000x reference)
#include <cuda_runtime.h>
#include <cstdint>
#include <cstddef>

#define H_DIM 2560
#define S_DIM 256
#define E_DIM 10
#define V_DIM 50257
#define LDE   50304            // padded expl stride = 393*128
#define R_DIM (S_DIM*E_DIM)    // 2560

// ---------------- scratch (static device allocations; no cudaMalloc) --------
__device__ float g_h[S_DIM*H_DIM];                 // rmsnorm output (tf32-rounded)
__device__ float g_eh[R_DIM*H_DIM];                // expert_hidden, row r=s*E+e (tf32-rounded)
__device__ float g_expl[(size_t)R_DIM*LDE];        // exp(logits)
__device__ float g_Z[R_DIM];                       // row sums of exp(logits)
__device__ float g_gate[S_DIM*E_DIM];              // gate softmax weights

__device__ __forceinline__ float tf32_rna(float x){
    uint32_t u; asm("cvt.rna.tf32.f32 %0, %1;" : "=r"(u) : "f"(x));
    return __uint_as_float(u);
}

// ---------------- kernel 1: rmsnorm + gate softmax ---------------------------
__global__ void prep_kernel(const float* __restrict__ hid,
                            const float* __restrict__ nscale,
                            const float* __restrict__ gateW){
    int s = blockIdx.x, t = threadIdx.x;
    __shared__ float red[256];
    __shared__ float gred[E_DIM][256];
    float x[10];
    float ss = 0.f;
#pragma unroll
    for (int j=0;j<10;j++){ x[j] = hid[s*H_DIM + t + j*256]; ss += x[j]*x[j]; }
    red[t] = ss; __syncthreads();
    for (int off=128; off; off>>=1){ if(t<off) red[t]+=red[t+off]; __syncthreads(); }
    float inv = rsqrtf(red[0]/(float)H_DIM + 1e-5f);
    float ga[E_DIM];
#pragma unroll
    for(int e=0;e<E_DIM;e++) ga[e]=0.f;
#pragma unroll
    for (int j=0;j<10;j++){
        int i = t + j*256;
        float h = x[j]*inv*nscale[i];
        g_h[s*H_DIM + i] = tf32_rna(h);
#pragma unroll
        for(int e=0;e<E_DIM;e++) ga[e] += h*gateW[i*E_DIM + e];
    }
#pragma unroll
    for(int e=0;e<E_DIM;e++) gred[e][t]=ga[e];
    __syncthreads();
    for(int off=128; off; off>>=1){
        if(t<off){
#pragma unroll
            for(int e=0;e<E_DIM;e++) gred[e][t]+=gred[e][t+off];
        }
        __syncthreads();
    }
    if (t==0){
        float m=-1e30f;
#pragma unroll
        for(int e=0;e<E_DIM;e++) m=fmaxf(m,gred[e][0]);
        float sum=0.f; float ex[E_DIM];
#pragma unroll
        for(int e=0;e<E_DIM;e++){ ex[e]=expf(gred[e][0]-m); sum+=ex[e]; }
#pragma unroll
        for(int e=0;e<E_DIM;e++) g_gate[s*E_DIM+e]=ex[e]/sum;
    }
}

// ---------------- tf32 GEMM --------------------------------------------------
#define TM 256
#define TN 128
#define TK 32
#define STAGES 3
#define A_ST 36       // smem row stride (floats) for A [m][k] tiles
#define B_ST_T 36     // B stored [n][k] (BT=true)
#define B_ST_N 132    // B stored [k][n] (BT=false)
#define A_FL (TM*A_ST)                 // 9216 floats
#define B_FL (TN*B_ST_T)               // 4608 floats (>= 32*132=4224)
#define STAGE_FL (A_FL + B_FL)         // 13824 floats
#define SMEM_BYTES (STAGE_FL*STAGES*4) // 165888 B

__device__ __forceinline__ void cp16(uint32_t d, const void* s){
    asm volatile("cp.async.cg.shared.global [%0], [%1], 16;\n" :: "r"(d), "l"(s));
}
__device__ __forceinline__ void cp16z(uint32_t d, const void* s, unsigned sz){
    asm volatile("cp.async.cg.shared.global [%0], [%1], 16, %2;\n" :: "r"(d), "l"(s), "r"(sz));
}
__device__ __forceinline__ void cp_commit(){ asm volatile("cp.async.commit_group;\n"); }

__device__ __forceinline__ void mma_tf32(float c[4], uint32_t a0,uint32_t a1,uint32_t a2,uint32_t a3,
                                         uint32_t b0,uint32_t b1){
    asm volatile("mma.sync.aligned.m16n8k8.row.col.f32.tf32.tf32.f32 "
        "{%0,%1,%2,%3},{%4,%5,%6,%7},{%8,%9},{%0,%1,%2,%3};\n"
        : "+f"(c[0]),"+f"(c[1]),"+f"(c[2]),"+f"(c[3])
        : "r"(a0),"r"(a1),"r"(a2),"r"(a3),"r"(b0),"r"(b1));
}

// C[M,N] = A[M,K] * B, A row-major (K contiguous).
// BT=true:  B is [Ntot,K] row-major (C = A·B^T), rows >= Ntot zero-filled.
// BT=false: B is [K,Ntot] row-major (C = A·B).
// Output row = globalRow*rowMul + z ; EXP => store expf(value), guarded col<Ntot.
template<bool BT, bool EXP>
__global__ __launch_bounds__(256)
void gemm_tf32_kernel(const float* __restrict__ A, const float* __restrict__ Bg,
                      float* __restrict__ C,
                      int Ntot, int K, int ldA, int ldB, int ldC,
                      int rowMul, long long bStride)
{
    extern __shared__ float smem[];
    const int tid = threadIdx.x;
    const int mBase = blockIdx.x*TM, nBase = blockIdx.y*TN;
    const int z = blockIdx.z;
    const float* B = Bg + (size_t)z*(size_t)bStride;
    const uint32_t sbase = (uint32_t)__cvta_generic_to_shared(smem);
    const int KT = K/TK;

    auto issue = [&](int kt, int st){
        uint32_t sA = sbase + (uint32_t)(st*STAGE_FL)*4u;
        uint32_t sB = sA + (uint32_t)A_FL*4u;
        // A tile: 256 rows x 32 k  -> 2048 16B chunks, 8 per thread
#pragma unroll
        for (int i=0;i<8;i++){
            int c = tid + i*256;
            int row = c>>3, kc=(c&7)*4;
            cp16(sA + (uint32_t)(row*A_ST+kc)*4u,
                 A + (size_t)(mBase+row)*ldA + kt*TK + kc);
        }
        if (BT){
#pragma unroll
            for (int i=0;i<4;i++){
                int c = tid + i*256;
                int row=c>>3, kc=(c&7)*4;
                int v = nBase + row;
                int vc = v < Ntot ? v : 0;
                unsigned sz = v < Ntot ? 16u : 0u;
                cp16z(sB + (uint32_t)(row*B_ST_T+kc)*4u,
                      B + (size_t)vc*ldB + kt*TK + kc, sz);
            }
        } else {
#pragma unroll
            for (int i=0;i<4;i++){
                int c = tid + i*256;
                int k=c>>5, nc=(c&31)*4;
                cp16(sB + (uint32_t)(k*B_ST_N+nc)*4u,
                     B + (size_t)(kt*TK+k)*ldB + nBase + nc);
            }
        }
    };

    issue(0,0); cp_commit();
    issue(1,1); cp_commit();

    const int warp = tid>>5, lane = tid&31;
    const int wm = warp & 3, wn = warp >> 2;     // 4 m-warps x 2 n-warps, 64x64 each
    const int gid = lane>>2, t4 = lane&3;

    float acc[4][8][4];
#pragma unroll
    for (int mi=0;mi<4;mi++)
#pragma unroll
        for(int ni=0;ni<8;ni++)
#pragma unroll
            for(int q=0;q<4;q++) acc[mi][ni][q]=0.f;

    const int aRow0 = wm*64 + gid;
    const int bCol0 = wn*64 + gid;

    for (int kt=0; kt<KT; kt++){
        asm volatile("cp.async.wait_group %0;\n"::"n"(STAGES-2));
        __syncthreads();
        if (kt + (STAGES-1) < KT) issue(kt+STAGES-1, (kt+STAGES-1)%STAGES);
        cp_commit();

        const uint32_t* uA = (const uint32_t*)(smem + (kt%STAGES)*STAGE_FL);
        const uint32_t* uB = uA + A_FL;
#pragma unroll
        for (int kk=0; kk<TK; kk+=8){
            uint32_t a[4][4], b[8][2];
#pragma unroll
            for (int mi=0;mi<4;mi++){
                int r0 = (aRow0 + mi*16)*A_ST + kk + t4;
                // PTX m16n8k8 tf32 A-fragment:
                //   a0=(g, t4)   a1=(g+8, t4)   a2=(g, t4+4)   a3=(g+8, t4+4)
                a[mi][0]=uA[r0];             // (g,   k+t4)
                a[mi][1]=uA[r0+8*A_ST];      // (g+8, k+t4)
                a[mi][2]=uA[r0+4];           // (g,   k+t4+4)
                a[mi][3]=uA[r0+8*A_ST+4];    // (g+8, k+t4+4)
            }
#pragma unroll
            for (int ni=0;ni<8;ni++){
                if (BT){
                    int c0 = (bCol0 + ni*8)*B_ST_T + kk + t4;
                    b[ni][0]=uB[c0]; b[ni][1]=uB[c0+4];
                } else {
                    int c0 = (kk+t4)*B_ST_N + bCol0 + ni*8;
                    b[ni][0]=uB[c0]; b[ni][1]=uB[c0+4*B_ST_N];
                }
            }
#pragma unroll
            for (int mi=0;mi<4;mi++)
#pragma unroll
                for (int ni=0;ni<8;ni++)
                    mma_tf32(acc[mi][ni], a[mi][0],a[mi][1],a[mi][2],a[mi][3],
                             b[ni][0],b[ni][1]);
        }
    }
    asm volatile("cp.async.wait_group 0;\n");

    // epilogue
    const int epiRow = mBase + wm*64 + gid;
    const int epiCol = nBase + wn*64 + t4*2;
#pragma unroll
    for (int mi=0;mi<4;mi++){
#pragma unroll
        for (int half=0; half<2; half++){
            int r = epiRow + mi*16 + half*8;
            size_t rowOff = (size_t)(r*rowMul + z)*(size_t)ldC;
#pragma unroll
            for (int ni=0;ni<8;ni++){
                int col = epiCol + ni*8;
                float v0 = acc[mi][ni][half*2+0];
                float v1 = acc[mi][ni][half*2+1];
                if (EXP){
                    if (col+1 < Ntot){
                        float2 p; p.x=__expf(v0); p.y=__expf(v1);
                        *(float2*)(C + rowOff + col) = p;
                    } else if (col < Ntot){
                        C[rowOff+col] = __expf(v0);
                    }
                } else {
                    float2 p; p.x = tf32_rna(v0); p.y = tf32_rna(v1);
                    *(float2*)(C + rowOff + col) = p;
                }
            }
        }
    }
}

// ---------------- kernel 4: per-(s,e) row sums of exp(logits) ---------------
__global__ void rowsum_kernel(){
    int r = blockIdx.x, t = threadIdx.x;
    const float* p = g_expl + (size_t)r*LDE;
    float s=0.f;
    for (int v=t; v<V_DIM; v+=256) s += p[v];
    __shared__ float red[256];
    red[t]=s; __syncthreads();
    for(int off=128;off;off>>=1){ if(t<off) red[t]+=red[t+off]; __syncthreads(); }
    if(t==0) g_Z[r]=red[0];
}

// ---------------- kernel 5: mixture + log ------------------------------------
__global__ void final_kernel(float* __restrict__ out){
    int s = blockIdx.y;
    int v = blockIdx.x*256 + threadIdx.x;
    __shared__ float w[E_DIM];
    if (threadIdx.x < E_DIM){
        int idx = s*E_DIM + threadIdx.x;
        w[threadIdx.x] = g_gate[idx] / g_Z[idx];
    }
    __syncthreads();
    if (v < V_DIM){
        const float* base = g_expl + (size_t)(s*E_DIM)*LDE + v;
        float acc = 0.f;
#pragma unroll
        for (int e=0;e<E_DIM;e++) acc += w[e]*base[(size_t)e*LDE];
        out[(size_t)s*V_DIM + v] = logf(acc + 1e-10f);
    }
}

// ---------------- launch -----------------------------------------------------
extern "C" void kernel_launch(void* const* d_in, const int* in_sizes, int n_in,
                              void* d_out, int out_size){
    const float* hid  = (const float*)d_in[0];   // (1,256,2560)
    const float* emb  = (const float*)d_in[1];   // (50257,2560)
    const float* nsc  = (const float*)d_in[2];   // (2560,)
    const float* expw = (const float*)d_in[3];   // (10,2560,2560)
    const float* gw   = (const float*)d_in[4];   // (2560,10)
    float* out = (float*)d_out;

    cudaFuncSetAttribute(gemm_tf32_kernel<false,false>,
                         cudaFuncAttributeMaxDynamicSharedMemorySize, SMEM_BYTES);
    cudaFuncSetAttribute(gemm_tf32_kernel<true,true>,
                         cudaFuncAttributeMaxDynamicSharedMemorySize, SMEM_BYTES);

    float *ph, *peh, *pexpl;
    cudaGetSymbolAddress((void**)&ph,    g_h);
    cudaGetSymbolAddress((void**)&peh,   g_eh);
    cudaGetSymbolAddress((void**)&pexpl, g_expl);

    // 1) rmsnorm + gate
    prep_kernel<<<S_DIM, 256>>>(hid, nsc, gw);

    // 2) expert_hidden: per expert e, C_e[256,2560] = h · W_e  (B = [K,N])
    {
        dim3 g(1, H_DIM/TN, E_DIM);  // (1,20,10)
        gemm_tf32_kernel<false,false><<<g, 256, SMEM_BYTES>>>(
            ph, expw, peh,
            /*Ntot=*/H_DIM, /*K=*/H_DIM, /*ldA=*/H_DIM, /*ldB=*/H_DIM, /*ldC=*/H_DIM,
            /*rowMul=*/E_DIM, /*bStride=*/(long long)H_DIM*H_DIM);
    }

    // 3) exp(logits): C[2560,V] = EH · Emb^T  (B = [V,K]), epilogue exp()
    {
        dim3 g(R_DIM/TM, (V_DIM + TN - 1)/TN, 1);  // (10,393,1) — M fastest for L2 B-reuse
        gemm_tf32_kernel<true,true><<<g, 256, SMEM_BYTES>>>(
            peh, emb, pexpl,
            /*Ntot=*/V_DIM, /*K=*/H_DIM, /*ldA=*/H_DIM, /*ldB=*/H_DIM, /*ldC=*/LDE,
            /*rowMul=*/1, /*bStride=*/0LL);
    }

    // 4) softmax denominators
    rowsum_kernel<<<R_DIM, 256>>>();

    // 5) mixture + log
    {
        dim3 g((V_DIM + 255)/256, S_DIM, 1);
        final_kernel<<<g, 256>>>(out);
    }
}

// round 8
// speedup vs baseline: 1.4291x; 1.4291x over previous
#include <cuda_runtime.h>
#include <cuda_bf16.h>
#include <cstdint>
#include <cstddef>

#define H_DIM 2560
#define S_DIM 256
#define E_DIM 10
#define V_DIM 50257
#define VPAD  50432            // 197*256 (embb row padding)
#define LDE   50304            // padded expl stride = 393*128
#define R_DIM (S_DIM*E_DIM)    // 2560

// ---------------- scratch (static device allocations) -----------------------
__device__ float g_h[S_DIM*H_DIM];
__device__ __nv_bfloat16 g_ehb[(size_t)R_DIM*H_DIM];       // GEMM1 out, bf16
__device__ __nv_bfloat16 g_embb[(size_t)VPAD*H_DIM];       // embedding bf16, padded
__device__ float g_expl[(size_t)R_DIM*LDE];                // exp(logits)
__device__ float g_Z[R_DIM];                               // row sums (atomic)
__device__ float g_gate[S_DIM*E_DIM];

__device__ __forceinline__ float tf32_rna(float x){
    uint32_t u; asm("cvt.rna.tf32.f32 %0, %1;" : "=r"(u) : "f"(x));
    return __uint_as_float(u);
}

__device__ __forceinline__ void cp16(uint32_t d, const void* s){
    asm volatile("cp.async.cg.shared.global [%0], [%1], 16;\n" :: "r"(d), "l"(s));
}
__device__ __forceinline__ void cp_commit(){ asm volatile("cp.async.commit_group;\n"); }

// ---------------- kernel 1: rmsnorm + gate softmax ---------------------------
__global__ void prep_kernel(const float* __restrict__ hid,
                            const float* __restrict__ nscale,
                            const float* __restrict__ gateW){
    int s = blockIdx.x, t = threadIdx.x;
    __shared__ float red[256];
    __shared__ float gred[E_DIM][256];
    float x[10];
    float ss = 0.f;
#pragma unroll
    for (int j=0;j<10;j++){ x[j] = hid[s*H_DIM + t + j*256]; ss += x[j]*x[j]; }
    red[t] = ss; __syncthreads();
    for (int off=128; off; off>>=1){ if(t<off) red[t]+=red[t+off]; __syncthreads(); }
    float inv = rsqrtf(red[0]/(float)H_DIM + 1e-5f);
    float ga[E_DIM];
#pragma unroll
    for(int e=0;e<E_DIM;e++) ga[e]=0.f;
#pragma unroll
    for (int j=0;j<10;j++){
        int i = t + j*256;
        float h = x[j]*inv*nscale[i];
        g_h[s*H_DIM + i] = tf32_rna(h);
#pragma unroll
        for(int e=0;e<E_DIM;e++) ga[e] += h*gateW[i*E_DIM + e];
    }
#pragma unroll
    for(int e=0;e<E_DIM;e++) gred[e][t]=ga[e];
    __syncthreads();
    for(int off=128; off; off>>=1){
        if(t<off){
#pragma unroll
            for(int e=0;e<E_DIM;e++) gred[e][t]+=gred[e][t+off];
        }
        __syncthreads();
    }
    if (t==0){
        float m=-1e30f;
#pragma unroll
        for(int e=0;e<E_DIM;e++) m=fmaxf(m,gred[e][0]);
        float sum=0.f; float ex[E_DIM];
#pragma unroll
        for(int e=0;e<E_DIM;e++){ ex[e]=expf(gred[e][0]-m); sum+=ex[e]; }
#pragma unroll
        for(int e=0;e<E_DIM;e++) g_gate[s*E_DIM+e]=ex[e]/sum;
    }
}

// ---------------- embedding fp32 -> bf16 (padded, zero tail) -----------------
__global__ void embconv_kernel(const float* __restrict__ emb){
    int row = blockIdx.x, t = threadIdx.x;
    __nv_bfloat162* dst = (__nv_bfloat162*)(g_embb + (size_t)row*H_DIM);
    if (row < V_DIM){
        const float2* src = (const float2*)(emb + (size_t)row*H_DIM);
        for (int i=t; i<H_DIM/2; i+=256){
            float2 v = src[i];
            dst[i] = __floats2bfloat162_rn(v.x, v.y);
        }
    } else {
        for (int i=t; i<H_DIM/2; i+=256) dst[i] = __floats2bfloat162_rn(0.f, 0.f);
    }
}

__global__ void zeroZ_kernel(){
    int i = blockIdx.x*256 + threadIdx.x;
    if (i < R_DIM) g_Z[i] = 0.f;
}

// ---------------- GEMM1: legacy tf32 mma, bf16 output ------------------------
#define TM 256
#define TN 128
#define TK 32
#define STAGES 3
#define A_ST 36
#define B_ST_N 132
#define A_FL (TM*A_ST)
#define B_FL (TN*36)
#define STAGE_FL (A_FL + B_FL)
#define SMEM1_BYTES (STAGE_FL*STAGES*4)

__device__ __forceinline__ void mma_tf32(float c[4], uint32_t a0,uint32_t a1,uint32_t a2,uint32_t a3,
                                         uint32_t b0,uint32_t b1){
    asm volatile("mma.sync.aligned.m16n8k8.row.col.f32.tf32.tf32.f32 "
        "{%0,%1,%2,%3},{%4,%5,%6,%7},{%8,%9},{%0,%1,%2,%3};\n"
        : "+f"(c[0]),"+f"(c[1]),"+f"(c[2]),"+f"(c[3])
        : "r"(a0),"r"(a1),"r"(a2),"r"(a3),"r"(b0),"r"(b1));
}

__global__ __launch_bounds__(256)
void gemm1_tf32_kernel(const float* __restrict__ A, const float* __restrict__ Bg,
                       __nv_bfloat16* __restrict__ C,
                       int K, int ldA, int ldB, int ldC)
{
    extern __shared__ float smem[];
    const int tid = threadIdx.x;
    const int mBase = blockIdx.x*TM, nBase = blockIdx.y*TN;
    const int z = blockIdx.z;
    const float* B = Bg + (size_t)z*(size_t)H_DIM*H_DIM;
    const uint32_t sbase = (uint32_t)__cvta_generic_to_shared(smem);
    const int KT = K/TK;

    auto issue = [&](int kt, int st){
        uint32_t sA = sbase + (uint32_t)(st*STAGE_FL)*4u;
        uint32_t sB = sA + (uint32_t)A_FL*4u;
#pragma unroll
        for (int i=0;i<8;i++){
            int c = tid + i*256;
            int row = c>>3, kc=(c&7)*4;
            cp16(sA + (uint32_t)(row*A_ST+kc)*4u,
                 A + (size_t)(mBase+row)*ldA + kt*TK + kc);
        }
#pragma unroll
        for (int i=0;i<4;i++){
            int c = tid + i*256;
            int k=c>>5, nc=(c&31)*4;
            cp16(sB + (uint32_t)(k*B_ST_N+nc)*4u,
                 B + (size_t)(kt*TK+k)*ldB + nBase + nc);
        }
    };

    issue(0,0); cp_commit();
    issue(1,1); cp_commit();

    const int warp = tid>>5, lane = tid&31;
    const int wm = warp & 3, wn = warp >> 2;
    const int gid = lane>>2, t4 = lane&3;

    float acc[4][8][4];
#pragma unroll
    for (int mi=0;mi<4;mi++)
#pragma unroll
        for(int ni=0;ni<8;ni++)
#pragma unroll
            for(int q=0;q<4;q++) acc[mi][ni][q]=0.f;

    const int aRow0 = wm*64 + gid;
    const int bCol0 = wn*64 + gid;

    for (int kt=0; kt<KT; kt++){
        asm volatile("cp.async.wait_group %0;\n"::"n"(STAGES-2));
        __syncthreads();
        if (kt + (STAGES-1) < KT) issue(kt+STAGES-1, (kt+STAGES-1)%STAGES);
        cp_commit();

        const uint32_t* uA = (const uint32_t*)(smem + (kt%STAGES)*STAGE_FL);
        const uint32_t* uB = uA + A_FL;
#pragma unroll
        for (int kk=0; kk<TK; kk+=8){
            uint32_t a[4][4], b[8][2];
#pragma unroll
            for (int mi=0;mi<4;mi++){
                int r0 = (aRow0 + mi*16)*A_ST + kk + t4;
                a[mi][0]=uA[r0];
                a[mi][1]=uA[r0+8*A_ST];
                a[mi][2]=uA[r0+4];
                a[mi][3]=uA[r0+8*A_ST+4];
            }
#pragma unroll
            for (int ni=0;ni<8;ni++){
                int c0 = (kk+t4)*B_ST_N + bCol0 + ni*8;
                b[ni][0]=uB[c0]; b[ni][1]=uB[c0+4*B_ST_N];
            }
#pragma unroll
            for (int mi=0;mi<4;mi++)
#pragma unroll
                for (int ni=0;ni<8;ni++)
                    mma_tf32(acc[mi][ni], a[mi][0],a[mi][1],a[mi][2],a[mi][3],
                             b[ni][0],b[ni][1]);
        }
    }
    asm volatile("cp.async.wait_group 0;\n");

    const int epiRow = mBase + wm*64 + gid;
    const int epiCol = nBase + wn*64 + t4*2;
#pragma unroll
    for (int mi=0;mi<4;mi++){
#pragma unroll
        for (int half=0; half<2; half++){
            int r = epiRow + mi*16 + half*8;
            size_t rowOff = (size_t)(r*E_DIM + z)*(size_t)ldC;
#pragma unroll
            for (int ni=0;ni<8;ni++){
                int col = epiCol + ni*8;
                __nv_bfloat162 p = __floats2bfloat162_rn(acc[mi][ni][half*2+0],
                                                         acc[mi][ni][half*2+1]);
                *(__nv_bfloat162*)(C + rowOff + col) = p;
            }
        }
    }
}

// ---------------- GEMM2: legacy bf16 m16n8k16, exp + rowsum epilogue ---------
// Cexp[r][v] = exp( sum_k A[r][k] * B[v][k] ); also g_Z[r] += row partials.
// A = g_ehb [2560,2560] bf16 row-major; B = g_embb [VPAD,2560] bf16 row-major.
#define TK2 32                 // bf16 k per tile (64 B rows)
#define A_ST2 40               // smem row stride in halves (20 words) -> conflict-free
#define A_W (TM*20)            // A tile words (5120)
#define B_W (TN*20)            // B tile words (2560)
#define STAGE_W (A_W + B_W)    // 7680 words
#define SMEM2_BYTES (STAGE_W*STAGES*4)   // 92160 B

__device__ __forceinline__ void mma_bf16(float c[4], uint32_t a0,uint32_t a1,uint32_t a2,uint32_t a3,
                                         uint32_t b0,uint32_t b1){
    asm volatile("mma.sync.aligned.m16n8k16.row.col.f32.bf16.bf16.f32 "
        "{%0,%1,%2,%3},{%4,%5,%6,%7},{%8,%9},{%0,%1,%2,%3};\n"
        : "+f"(c[0]),"+f"(c[1]),"+f"(c[2]),"+f"(c[3])
        : "r"(a0),"r"(a1),"r"(a2),"r"(a3),"r"(b0),"r"(b1));
}

__global__ __launch_bounds__(256)
void gemm2_bf16_kernel(const __nv_bfloat16* __restrict__ A,
                       const __nv_bfloat16* __restrict__ B,
                       float* __restrict__ Cexp, int Ntot)
{
    extern __shared__ uint32_t smw[];
    const int tid = threadIdx.x;
    const int mBase = blockIdx.x*TM, nBase = blockIdx.y*TN;
    const uint32_t sbase = (uint32_t)__cvta_generic_to_shared(smw);
    const int KT = H_DIM/TK2;   // 80

    auto issue = [&](int kt, int st){
        uint32_t sA = sbase + (uint32_t)(st*STAGE_W)*4u;
        uint32_t sB = sA + (uint32_t)A_W*4u;
        // A: 256 rows x 64 B -> 1024 chunks of 16B, 4/thread
#pragma unroll
        for (int i=0;i<4;i++){
            int c = tid + i*256;
            int row = c>>2, ch = c&3;                 // ch*16 B = ch*8 halves
            cp16(sA + (uint32_t)(row*80 + ch*16),
                 A + (size_t)(mBase+row)*H_DIM + kt*TK2 + ch*8);
        }
        // B: 128 rows x 64 B -> 512 chunks, 2/thread
#pragma unroll
        for (int i=0;i<2;i++){
            int c = tid + i*256;
            int row = c>>2, ch = c&3;
            cp16(sB + (uint32_t)(row*80 + ch*16),
                 B + (size_t)(nBase+row)*H_DIM + kt*TK2 + ch*8);
        }
    };

    issue(0,0); cp_commit();
    issue(1,1); cp_commit();

    const int warp = tid>>5, lane = tid&31;
    const int wm = warp & 3, wn = warp >> 2;    // 4x2 warps, 64x64 each
    const int gid = lane>>2, t4 = lane&3;

    float acc[4][8][4];
#pragma unroll
    for (int mi=0;mi<4;mi++)
#pragma unroll
        for(int ni=0;ni<8;ni++)
#pragma unroll
            for(int q=0;q<4;q++) acc[mi][ni][q]=0.f;

    const int aRow0 = wm*64 + gid;
    const int bCol0 = wn*64 + gid;

    for (int kt=0; kt<KT; kt++){
        asm volatile("cp.async.wait_group %0;\n"::"n"(STAGES-2));
        __syncthreads();
        if (kt + (STAGES-1) < KT) issue(kt+STAGES-1, (kt+STAGES-1)%STAGES);
        cp_commit();

        const uint32_t* uA = smw + (kt%STAGES)*STAGE_W;
        const uint32_t* uB = uA + A_W;
#pragma unroll
        for (int k2=0; k2<2; k2++){            // two k16 steps per TK2=32
            const int kw = k2*8 + t4;          // word offset in row
            uint32_t a[4][4], b[8][2];
#pragma unroll
            for (int mi=0;mi<4;mi++){
                int r0 = (aRow0 + mi*16)*20 + kw;
                // m16n8k16 bf16 A-frag: a0=(g,2t4..), a1=(g+8,..), a2=(g,2t4+8..), a3=(g+8,..)
                a[mi][0]=uA[r0];
                a[mi][1]=uA[r0+160];           // +8 rows * 20 words
                a[mi][2]=uA[r0+4];             // +8 halves = +4 words
                a[mi][3]=uA[r0+164];
            }
#pragma unroll
            for (int ni=0;ni<8;ni++){
                int c0 = (bCol0 + ni*8)*20 + kw;
                b[ni][0]=uB[c0]; b[ni][1]=uB[c0+4];
            }
#pragma unroll
            for (int mi=0;mi<4;mi++)
#pragma unroll
                for (int ni=0;ni<8;ni++)
                    mma_bf16(acc[mi][ni], a[mi][0],a[mi][1],a[mi][2],a[mi][3],
                             b[ni][0],b[ni][1]);
        }
    }
    asm volatile("cp.async.wait_group 0;\n");

    // epilogue: exp + store + fused row-sum (shfl over t4 group, 1 atomic per slice)
    const int epiRow = mBase + wm*64 + gid;
    const int epiCol = nBase + wn*64 + t4*2;
#pragma unroll
    for (int mi=0;mi<4;mi++){
#pragma unroll
        for (int half=0; half<2; half++){
            int r = epiRow + mi*16 + half*8;
            size_t rowOff = (size_t)r*(size_t)LDE;
            float rsum = 0.f;
#pragma unroll
            for (int ni=0;ni<8;ni++){
                int col = epiCol + ni*8;
                float v0 = __expf(acc[mi][ni][half*2+0]);
                float v1 = __expf(acc[mi][ni][half*2+1]);
                if (col+1 < Ntot){
                    float2 p; p.x=v0; p.y=v1;
                    *(float2*)(Cexp + rowOff + col) = p;
                    rsum += v0 + v1;
                } else if (col < Ntot){
                    Cexp[rowOff+col] = v0;
                    rsum += v0;
                }
            }
            rsum += __shfl_xor_sync(0xffffffffu, rsum, 1);
            rsum += __shfl_xor_sync(0xffffffffu, rsum, 2);
            if (t4 == 0) atomicAdd(&g_Z[r], rsum);
        }
    }
}

// ---------------- final: mixture + log ---------------------------------------
__global__ void final_kernel(float* __restrict__ out){
    int s = blockIdx.y;
    int v = blockIdx.x*256 + threadIdx.x;
    __shared__ float w[E_DIM];
    if (threadIdx.x < E_DIM){
        int idx = s*E_DIM + threadIdx.x;
        w[threadIdx.x] = g_gate[idx] / g_Z[idx];
    }
    __syncthreads();
    if (v < V_DIM){
        const float* base = g_expl + (size_t)(s*E_DIM)*LDE + v;
        float acc = 0.f;
#pragma unroll
        for (int e=0;e<E_DIM;e++) acc += w[e]*base[(size_t)e*LDE];
        out[(size_t)s*V_DIM + v] = logf(acc + 1e-10f);
    }
}

// ---------------- launch -----------------------------------------------------
extern "C" void kernel_launch(void* const* d_in, const int* in_sizes, int n_in,
                              void* d_out, int out_size){
    const float* hid  = (const float*)d_in[0];
    const float* emb  = (const float*)d_in[1];
    const float* nsc  = (const float*)d_in[2];
    const float* expw = (const float*)d_in[3];
    const float* gw   = (const float*)d_in[4];
    float* out = (float*)d_out;

    cudaFuncSetAttribute(gemm1_tf32_kernel,
                         cudaFuncAttributeMaxDynamicSharedMemorySize, SMEM1_BYTES);
    cudaFuncSetAttribute(gemm2_bf16_kernel,
                         cudaFuncAttributeMaxDynamicSharedMemorySize, SMEM2_BYTES);

    float *ph, *pexpl;
    __nv_bfloat16 *pehb, *pembb;
    cudaGetSymbolAddress((void**)&ph,    g_h);
    cudaGetSymbolAddress((void**)&pehb,  g_ehb);
    cudaGetSymbolAddress((void**)&pembb, g_embb);
    cudaGetSymbolAddress((void**)&pexpl, g_expl);

    // 1) rmsnorm + gate softmax
    prep_kernel<<<S_DIM, 256>>>(hid, nsc, gw);

    // 2) embedding -> bf16 (padded rows zeroed) ; zero Z accumulators
    embconv_kernel<<<VPAD, 256>>>(emb);
    zeroZ_kernel<<<(R_DIM+255)/256, 256>>>();

    // 3) expert_hidden (tf32), bf16 out; row r = s*E + e
    {
        dim3 g(1, H_DIM/TN, E_DIM);
        gemm1_tf32_kernel<<<g, 256, SMEM1_BYTES>>>(
            ph, expw, pehb, H_DIM, H_DIM, H_DIM, H_DIM);
    }

    // 4) exp(logits) bf16 tensor cores + fused rowsum; M fastest for L2 B reuse
    {
        dim3 g(R_DIM/TM, (V_DIM + TN - 1)/TN, 1);   // (10, 393)
        gemm2_bf16_kernel<<<g, 256, SMEM2_BYTES>>>(pehb, pembb, pexpl, V_DIM);
    }

    // 5) mixture + log
    {
        dim3 g((V_DIM + 255)/256, S_DIM, 1);
        final_kernel<<<g, 256>>>(out);
    }
}